// round 10
// baseline (speedup 1.0000x reference)
#include <cuda_runtime.h>
#include <cstdint>

// IDWT1D (Haar synthesis) — 2-tap banded A => streaming butterfly, now as a
// cp.async.bulk (TMA) tile pipeline.
//
//   out[b,2i  ,c] = A[0,0]*x[b,i,c] + A[M,0]*x[b,i,C+c]
//   out[b,2i+1,c] = A[0,1]*x[b,i,c] + A[M,1]*x[b,i,C+c]
//
// Row = 32 contiguous floats [approx16|detail16] -> the two output rows occupy
// the SAME 32-float span (even half | odd half). Tile-local transform.
//
// R3..R9: every SIMT LDG/STG variant (MLP 2..4, dense or split, occ 38..75%)
// pinned at ~8.3us with ALL pipes ~25% -> the per-request SIMT path itself is
// the equilibrium. R10: one CTA = one 16KB tile; ONE bulk load + SMEM
// butterfly + ONE bulk store. 1024 CTAs x 32KB smem ~= 7 CTAs/SM = 1 wave,
// load/compute/store overlap across resident CTAs.

static constexpr int TILE_V4 = 1024;   // float4 per tile = 16KB

__device__ __forceinline__ uint32_t smem_u32(const void* p) {
    return (uint32_t)__cvta_generic_to_shared(p);
}

__device__ __forceinline__ void mbar_wait_parity0(uint32_t mb) {
    asm volatile(
        "{\n\t"
        ".reg .pred P;\n\t"
        "W_%=:\n\t"
        "mbarrier.try_wait.parity.acquire.cta.shared::cta.b64 P, [%0], 0, 0x989680;\n\t"
        "@P bra D_%=;\n\t"
        "bra W_%=;\n\t"
        "D_%=:\n\t"
        "}"
        :: "r"(mb) : "memory");
}

__global__ void __launch_bounds__(256)
idwt_haar_tma_kernel(const float* __restrict__ x,
                     const float* __restrict__ A,
                     float* __restrict__ out,
                     unsigned n_vec4,          // total float4 count (B*M*8)
                     unsigned highpass_row)    // M*N: flat index of A[M,0]
{
    __shared__ alignas(128) float4 s_in[TILE_V4];    // 16KB
    __shared__ alignas(128) float4 s_out[TILE_V4];   // 16KB
    __shared__ alignas(8)   uint64_t mbar;

    const unsigned base  = blockIdx.x * (unsigned)TILE_V4;  // tile start (f4)
    unsigned count = n_vec4 - base;                          // f4 in this tile
    if (count > (unsigned)TILE_V4) count = (unsigned)TILE_V4;
    const unsigned bytes = count * 16u;                      // multiple of 128

    const int tid = threadIdx.x;
    const uint32_t mb = smem_u32(&mbar);

    if (tid == 0) {
        asm volatile("mbarrier.init.shared.b64 [%0], 1;" :: "r"(mb) : "memory");
    }
    __syncthreads();

    if (tid == 0) {
        asm volatile("mbarrier.arrive.expect_tx.shared.b64 _, [%0], %1;"
                     :: "r"(mb), "r"(bytes) : "memory");
        asm volatile(
            "cp.async.bulk.shared::cta.global.mbarrier::complete_tx::bytes "
            "[%0], [%1], %2, [%3];"
            :: "r"(smem_u32(s_in)),
               "l"(x + (size_t)base * 4),
               "r"(bytes), "r"(mb)
            : "memory");
    }

    // Filter taps (overlaps with the bulk load).
    const float h00 = __ldg(&A[0]);                 // A[0,0]
    const float h01 = __ldg(&A[1]);                 // A[0,1]
    const float h10 = __ldg(&A[highpass_row]);      // A[M,0]
    const float h11 = __ldg(&A[highpass_row + 1]);  // A[M,1]

    mbar_wait_parity0(mb);

    // Butterfly in SMEM. Tile is whole rows (count % 8 == 0 since rows are
    // 8 float4 and n_vec4, base are multiples of 8). Output f4 i in slot s:
    //   s<4 : h00*approx + h10*detail   (even row half)
    //   s>=4: h01*approx + h11*detail   (odd  row half)
    #pragma unroll
    for (int k = 0; k < TILE_V4 / 256; k++) {
        const unsigned i = (unsigned)tid + (unsigned)k * 256u;
        if (i < count) {
            const unsigned rowb = i & ~7u;
            const unsigned s    = i & 7u;
            const float4 a = s_in[rowb + (s & 3u)];
            const float4 d = s_in[rowb + 4u + (s & 3u)];
            const float ta = (s < 4u) ? h00 : h01;
            const float tb = (s < 4u) ? h10 : h11;
            float4 r;
            r.x = ta * a.x + tb * d.x;
            r.y = ta * a.y + tb * d.y;
            r.z = ta * a.z + tb * d.z;
            r.w = ta * a.w + tb * d.w;
            s_out[i] = r;
        }
    }

    // Make generic-proxy STS visible to the async proxy, then bulk store.
    asm volatile("fence.proxy.async.shared::cta;" ::: "memory");
    __syncthreads();

    if (tid == 0) {
        asm volatile(
            "cp.async.bulk.global.shared::cta.bulk_group [%0], [%1], %2;"
            :: "l"(out + (size_t)base * 4),
               "r"(smem_u32(s_out)),
               "r"(bytes)
            : "memory");
        asm volatile("cp.async.bulk.commit_group;" ::: "memory");
        // Ensure the bulk store has consumed s_out before the CTA can retire.
        asm volatile("cp.async.bulk.wait_group.read 0;" ::: "memory");
    }
}

extern "C" void kernel_launch(void* const* d_in, const int* in_sizes, int n_in,
                              void* d_out, int out_size)
{
    const float* x = (const float*)d_in[0];
    const float* A = (const float*)d_in[1];
    float* out     = (float*)d_out;

    // A is (N, N): recover N from its element count (power of two).
    long long a_elems = in_sizes[1];
    long long N = 1;
    while (N * N < a_elems) N <<= 1;          // 4096 at default shape
    const long long M = N >> 1;
    const unsigned highpass_row = (unsigned)(M * N);   // flat index of A[M,0]

    const unsigned n_vec4 = (unsigned)(in_sizes[0] / 4);   // 1048576 default
    const unsigned blocks = (n_vec4 + TILE_V4 - 1) / TILE_V4;  // 1024 default

    idwt_haar_tma_kernel<<<blocks, 256>>>(x, A, out, n_vec4, highpass_row);
}

// round 11
// speedup vs baseline: 1.0144x; 1.0144x over previous
#include <cuda_runtime.h>
#include <cstdint>

// IDWT1D (Haar synthesis) — 2-tap banded A => streaming butterfly.
// R11: HYBRID path. Bulk (TMA) load into SMEM; butterfly computed from SMEM;
// dense STG.128 stores straight from registers (no s_out, no proxy fence, no
// bulk-store wait). Loads ride the async queue, stores ride the LSU queue.
//
//   out[b,2i  ,c] = A[0,0]*x[b,i,c] + A[M,0]*x[b,i,C+c]
//   out[b,2i+1,c] = A[0,1]*x[b,i,c] + A[M,1]*x[b,i,C+c]
//
// Row = 32 contiguous floats [approx16|detail16]; both output rows occupy the
// SAME 32-float span (even half | odd half). Tile-local transform.
//
// History: R3..R9 SIMT variants and R10 full-TMA all pinned at 8.3-9.0us with
// every pipe ~25%. This round splits traffic across both memory paths and
// shortens the per-CTA dependency chain.

static constexpr int TILE_V4 = 1024;   // float4 per tile = 16KB

__device__ __forceinline__ uint32_t smem_u32(const void* p) {
    return (uint32_t)__cvta_generic_to_shared(p);
}

__device__ __forceinline__ void mbar_wait_parity0(uint32_t mb) {
    asm volatile(
        "{\n\t"
        ".reg .pred P;\n\t"
        "W_%=:\n\t"
        "mbarrier.try_wait.parity.acquire.cta.shared::cta.b64 P, [%0], 0, 0x989680;\n\t"
        "@P bra D_%=;\n\t"
        "bra W_%=;\n\t"
        "D_%=:\n\t"
        "}"
        :: "r"(mb) : "memory");
}

__global__ void __launch_bounds__(256)
idwt_haar_hybrid_kernel(const float* __restrict__ x,
                        const float* __restrict__ A,
                        float4* __restrict__ out,
                        unsigned n_vec4,          // total float4 count
                        unsigned highpass_row)    // M*N: flat index of A[M,0]
{
    __shared__ alignas(128) float4 s_in[TILE_V4];    // 16KB
    __shared__ alignas(8)   uint64_t mbar;

    const unsigned base  = blockIdx.x * (unsigned)TILE_V4;  // tile start (f4)
    unsigned count = n_vec4 - base;                          // f4 in this tile
    if (count > (unsigned)TILE_V4) count = (unsigned)TILE_V4;
    const unsigned bytes = count * 16u;                      // multiple of 128

    const int tid = threadIdx.x;
    const uint32_t mb = smem_u32(&mbar);

    if (tid == 0) {
        asm volatile("mbarrier.init.shared.b64 [%0], 1;" :: "r"(mb) : "memory");
    }
    __syncthreads();

    if (tid == 0) {
        asm volatile("mbarrier.arrive.expect_tx.shared.b64 _, [%0], %1;"
                     :: "r"(mb), "r"(bytes) : "memory");
        asm volatile(
            "cp.async.bulk.shared::cta.global.mbarrier::complete_tx::bytes "
            "[%0], [%1], %2, [%3];"
            :: "r"(smem_u32(s_in)),
               "l"(x + (size_t)base * 4),
               "r"(bytes), "r"(mb)
            : "memory");
    }

    // Filter taps (overlap with the bulk load).
    const float h00 = __ldg(&A[0]);                 // A[0,0]
    const float h01 = __ldg(&A[1]);                 // A[0,1]
    const float h10 = __ldg(&A[highpass_row]);      // A[M,0]
    const float h11 = __ldg(&A[highpass_row + 1]);  // A[M,1]

    mbar_wait_parity0(mb);

    // Butterfly from SMEM, store straight to GMEM (dense STG.128).
    // Output f4 i (slot s = i&7):
    //   s<4 : h00*approx + h10*detail   (even row half)
    //   s>=4: h01*approx + h11*detail   (odd  row half)
    // approx at rowb+(s&3), detail at rowb+4+(s&3). Two lanes share each LDS
    // address (broadcast, conflict-free).
    #pragma unroll
    for (int k = 0; k < TILE_V4 / 256; k++) {
        const unsigned i = (unsigned)tid + (unsigned)k * 256u;
        if (i < count) {
            const unsigned rowb = i & ~7u;
            const unsigned s    = i & 7u;
            const float4 a = s_in[rowb + (s & 3u)];
            const float4 d = s_in[rowb + 4u + (s & 3u)];
            const float ta = (s < 4u) ? h00 : h01;
            const float tb = (s < 4u) ? h10 : h11;
            float4 r;
            r.x = ta * a.x + tb * d.x;
            r.y = ta * a.y + tb * d.y;
            r.z = ta * a.z + tb * d.z;
            r.w = ta * a.w + tb * d.w;
            out[base + i] = r;      // fire-and-forget, dense
        }
    }
}

extern "C" void kernel_launch(void* const* d_in, const int* in_sizes, int n_in,
                              void* d_out, int out_size)
{
    const float* x = (const float*)d_in[0];
    const float* A = (const float*)d_in[1];
    float4* out    = (float4*)d_out;

    // A is (N, N): recover N from its element count (power of two).
    long long a_elems = in_sizes[1];
    long long N = 1;
    while (N * N < a_elems) N <<= 1;          // 4096 at default shape
    const long long M = N >> 1;
    const unsigned highpass_row = (unsigned)(M * N);   // flat index of A[M,0]

    const unsigned n_vec4 = (unsigned)(in_sizes[0] / 4);   // 1048576 default
    const unsigned blocks = (n_vec4 + TILE_V4 - 1) / TILE_V4;  // 1024 default

    idwt_haar_hybrid_kernel<<<blocks, 256>>>(x, A, out, n_vec4, highpass_row);
}

// round 12
// speedup vs baseline: 1.0181x; 1.0036x over previous
#include <cuda_runtime.h>

// IDWT1D (Haar synthesis) — 2-tap banded A => streaming butterfly.
//
//   out[b,2i  ,c] = A[0,0]*x[b,i,c] + A[M,0]*x[b,i,C+c]
//   out[b,2i+1,c] = A[0,1]*x[b,i,c] + A[M,1]*x[b,i,C+c]
//
// Row = 32 contiguous floats [approx16|detail16]; both output rows occupy the
// SAME 32-float span (even half | odd half).
//
// R12: PERSISTENT ONE-WAVE kernel. Every prior config (R3..R11: SIMT dense/
// split, MLP 2..4, TMA, hybrid) ran 1.3-2.3 waves of short-lived CTAs and
// pinned at 8.3-9.0us with all pipes ~25%. This round removes CTA turnover
// entirely: grid = 148 SMs x 6 CTAs, each thread grid-strides the dense
// float4 stream (R9's access pattern: thread g <-> float4 g; lane slot s=g&7,
// s<4 approx / s>=4 detail; partner via shfl_xor(4); store back to the same
// offset). Unrolled by 2 with front-batched loads.

__device__ __forceinline__ float4 shfl4_xor4(float4 v) {
    float4 p;
    p.x = __shfl_xor_sync(0xFFFFFFFFu, v.x, 4);
    p.y = __shfl_xor_sync(0xFFFFFFFFu, v.y, 4);
    p.z = __shfl_xor_sync(0xFFFFFFFFu, v.z, 4);
    p.w = __shfl_xor_sync(0xFFFFFFFFu, v.w, 4);
    return p;
}

__global__ void __launch_bounds__(256, 6)
idwt_haar_persist_kernel(const float4* __restrict__ xin,
                         const float* __restrict__ A,
                         float4* __restrict__ o,
                         unsigned n_vec4,          // total float4 count
                         unsigned highpass_row)    // M*N: flat index of A[M,0]
{
    const float h00 = __ldg(&A[0]);                 // A[0,0]
    const float h01 = __ldg(&A[1]);                 // A[0,1]
    const float h10 = __ldg(&A[highpass_row]);      // A[M,0]
    const float h11 = __ldg(&A[highpass_row + 1]);  // A[M,1]

    const unsigned G   = gridDim.x * blockDim.x;    // total threads (stride)
    const unsigned g0  = blockIdx.x * blockDim.x + threadIdx.x;

    // Lane role is invariant across iterations: G % 8 == 0, so (g & 7) is
    // constant per thread. slots 0-3 hold approx, 4-7 hold detail.
    const bool isA = (g0 & 4u) == 0u;
    const float ta = isA ? h00 : h01;   // tap on the approx value
    const float tb = isA ? h10 : h11;   // tap on the detail value

    unsigned g = g0;

    // Unrolled-by-2 main loop: two dense front-batched loads per trip.
    // Whole warps stay together (n_vec4 % 8 == 0 and G % 32 == 0), so the
    // full-mask shuffles are safe on every taken path.
    for (; g + G < n_vec4; g += 2u * G) {
        const float4 v0 = xin[g];          // dense: 4 full 128B lines/warp
        const float4 v1 = xin[g + G];

        const float4 p0 = shfl4_xor4(v0);
        const float4 p1 = shfl4_xor4(v1);

        const float4 aa0 = isA ? v0 : p0;
        const float4 dd0 = isA ? p0 : v0;
        const float4 aa1 = isA ? v1 : p1;
        const float4 dd1 = isA ? p1 : v1;

        float4 r0, r1;
        r0.x = ta * aa0.x + tb * dd0.x;    r1.x = ta * aa1.x + tb * dd1.x;
        r0.y = ta * aa0.y + tb * dd0.y;    r1.y = ta * aa1.y + tb * dd1.y;
        r0.z = ta * aa0.z + tb * dd0.z;    r1.z = ta * aa1.z + tb * dd1.z;
        r0.w = ta * aa0.w + tb * dd0.w;    r1.w = ta * aa1.w + tb * dd1.w;

        o[g]     = r0;
        o[g + G] = r1;
    }

    // Remainder: at most one more item per thread.
    if (g < n_vec4) {
        const float4 v0 = xin[g];
        const float4 p0 = shfl4_xor4(v0);
        const float4 aa0 = isA ? v0 : p0;
        const float4 dd0 = isA ? p0 : v0;
        float4 r0;
        r0.x = ta * aa0.x + tb * dd0.x;
        r0.y = ta * aa0.y + tb * dd0.y;
        r0.z = ta * aa0.z + tb * dd0.z;
        r0.w = ta * aa0.w + tb * dd0.w;
        o[g] = r0;
    }
}

extern "C" void kernel_launch(void* const* d_in, const int* in_sizes, int n_in,
                              void* d_out, int out_size)
{
    const float4* x = (const float4*)d_in[0];
    const float*  A = (const float*)d_in[1];
    float4* out     = (float4*)d_out;

    // A is (N, N): recover N from its element count (power of two).
    long long a_elems = in_sizes[1];
    long long N = 1;
    while (N * N < a_elems) N <<= 1;          // 4096 at default shape
    const long long M = N >> 1;
    const unsigned highpass_row = (unsigned)(M * N);   // flat index of A[M,0]

    const unsigned n_vec4 = (unsigned)(in_sizes[0] / 4);   // 1048576 default

    // One resident wave: 148 SMs x 6 CTAs/SM (launch_bounds(256,6)).
    const int threads = 256;
    unsigned blocks = 148u * 6u;                            // 888
    // Never launch more threads than items (tiny-shape safety).
    const unsigned max_blocks = (n_vec4 + threads - 1) / threads;
    if (blocks > max_blocks) blocks = max_blocks;
    if (blocks < 1) blocks = 1;

    idwt_haar_persist_kernel<<<blocks, threads>>>(x, A, out, n_vec4, highpass_row);
}